// round 4
// baseline (speedup 1.0000x reference)
#include <cuda_runtime.h>
#include <math.h>

// Problem constants
#define BB   64     // batch
#define NN   100    // nodes
#define LL   32     // feature dim (stays 32 after each MP step since NODE_SIZES[1]==32)
#define E1   64     // edge hidden / output dim
#define NH   64     // node hidden dim
#define ND   32     // node output dim
#define ALPHAV 0.1f

// Scratch (device globals — no allocation allowed)
__device__ float g_hA[BB*NN*LL];
__device__ float g_hB[BB*NN*LL];
__device__ float g_U [BB*NN*E1];
__device__ float g_V [BB*NN*E1];
__device__ float g_agg[BB*NN*E1];

__device__ __forceinline__ float lrelu(float x) { return fmaxf(x, ALPHAV * x); }

// ---------------------------------------------------------------------------
// h = (x @ lin_w + lin_b).reshape(B, N, L)   -> g_hA
// ---------------------------------------------------------------------------
__global__ void lin_kernel(const float* __restrict__ x,
                           const float* __restrict__ w,
                           const float* __restrict__ b)
{
    int idx = blockIdx.x * blockDim.x + threadIdx.x;   // < B*3200
    int bb  = idx / (NN * LL);
    int o   = idx % (NN * LL);
    float acc = b[o];
    #pragma unroll
    for (int k = 0; k < LL; k++)
        acc = fmaf(x[bb * LL + k], w[k * (NN * LL) + o], acc);
    g_hA[idx] = acc;
}

// ---------------------------------------------------------------------------
// Per-node edge-layer0 partials:
//   U[n,c] = b0[c] + sum_m h[n,m] * W0[m,c]          (xi rows 0..31)
//   V[n,c] =         sum_m h[n,m] * W0[32+m,c]       (xj rows 32..63)
// ---------------------------------------------------------------------------
__global__ void uv_kernel(const float* __restrict__ h,
                          const float* __restrict__ w0,
                          const float* __restrict__ b0)
{
    int node = blockIdx.x;          // < B*N
    int t    = threadIdx.x;         // 128 threads
    __shared__ float hs[LL];
    if (t < LL) hs[t] = h[node * LL + t];
    __syncthreads();

    int c = t & 63;
    const float* w = w0 + ((t < 64) ? 0 : (LL * E1));
    float acc = (t < 64) ? b0[c] : 0.0f;
    #pragma unroll
    for (int m = 0; m < LL; m++)
        acc = fmaf(hs[m], w[m * E1 + c], acc);
    if (t < 64) g_U[node * E1 + c] = acc;
    else        g_V[node * E1 + c] = acc;
}

// ---------------------------------------------------------------------------
// Edge kernel: for each (b, i), agg[b,i,c] = sum_j lrelu( lrelu(U_i + V_j +
//              dist(i,j)*wd + b0) @ W1 + b1 )[c]
// Block: 4 i-values (groups of 64 channel-threads), 256 threads.
// ---------------------------------------------------------------------------
__global__ __launch_bounds__(256, 2)
void edge_kernel(const float* __restrict__ h,
                 const float* __restrict__ ew0,   // (65,64) — only row 64 (dist weight) used
                 const float* __restrict__ ew1,   // (64,64)
                 const float* __restrict__ eb1)   // (64)
{
    __shared__ float hjs[NN][LL + 1];              // padded: conflict-free column reads
    __shared__ float Vs[NN][E1];
    __shared__ float dists[4][NN];
    __shared__ __align__(16) float act0[4][2][E1]; // double-buffered per group

    int bb = blockIdx.y;                 // batch
    int i0 = blockIdx.x * 4;             // first node of this block (25*4 == 100)
    int t  = threadIdx.x;
    int g  = t >> 6;                     // group 0..3
    int c  = t & 63;                     // channel
    int i  = i0 + g;                     // this group's node

    // Stage h rows and V rows for the whole batch-b node set
    for (int idx = t; idx < NN * LL; idx += 256) {
        int j = idx / LL, m = idx % LL;
        hjs[j][m] = h[(bb * NN + j) * LL + m];
    }
    for (int idx = t; idx < NN * E1; idx += 256)
        Vs[idx >> 6][idx & 63] = g_V[bb * NN * E1 + idx];

    float Uik = g_U[(bb * NN + i) * E1 + c];  // includes b0
    float wdc = ew0[64 * E1 + c];             // dist weight row
    float b1c = eb1[c];
    float w1r[E1];                            // W1 column c in registers
    #pragma unroll
    for (int k = 0; k < E1; k++) w1r[k] = ew1[k * E1 + c];
    __syncthreads();

    // dist(i, j) for all j (per group)
    for (int j = c; j < NN; j += 64) {
        float s = 0.0f;
        #pragma unroll
        for (int m = 0; m < LL; m++) {
            float d = hjs[j][m] - hjs[i][m];
            s = fmaf(d, d, s);
        }
        dists[g][j] = sqrtf(s + 1e-12f);
    }
    __syncthreads();

    float aggc = 0.0f;
    for (int j = 0; j < NN; j++) {
        // layer0 (factored): one value per thread, shared with the group
        float tv = fmaf(dists[g][j], wdc, Uik + Vs[j][c]);
        act0[g][j & 1][c] = fmaxf(tv, ALPHAV * tv);
        __syncthreads();   // single barrier per j (double-buffered act0)

        // layer1: 64 FMAs, act0 via float4 broadcast loads, W1 in registers
        float sum = b1c;
        const float* ap = act0[g][j & 1];
        #pragma unroll
        for (int kk = 0; kk < E1; kk += 4) {
            float4 a = *reinterpret_cast<const float4*>(ap + kk);
            sum = fmaf(a.x, w1r[kk + 0], sum);
            sum = fmaf(a.y, w1r[kk + 1], sum);
            sum = fmaf(a.z, w1r[kk + 2], sum);
            sum = fmaf(a.w, w1r[kk + 3], sum);
        }
        aggc += fmaxf(sum, ALPHAV * sum);
    }
    g_agg[(bb * NN + i) * E1 + c] = aggc;
}

// ---------------------------------------------------------------------------
// Node MLP: h_out = lrelu( lrelu( [h, agg] @ W0 + b0 ) @ W1 + b1 )
// ---------------------------------------------------------------------------
__global__ void node_kernel(const float* __restrict__ h,
                            const float* __restrict__ w0,
                            const float* __restrict__ b0,
                            const float* __restrict__ w1,
                            const float* __restrict__ b1,
                            float* __restrict__ hout)
{
    int node = blockIdx.x;
    int c    = threadIdx.x;   // 64
    __shared__ float z[LL + E1];   // 96
    __shared__ float t0[NH];

    if (c < LL) z[c] = h[node * LL + c];
    z[LL + c] = g_agg[node * E1 + c];
    __syncthreads();

    float acc = b0[c];
    #pragma unroll
    for (int m = 0; m < LL + E1; m++)
        acc = fmaf(z[m], w0[m * NH + c], acc);
    t0[c] = fmaxf(acc, ALPHAV * acc);
    __syncthreads();

    if (c < ND) {
        float s = b1[c];
        #pragma unroll
        for (int k = 0; k < NH; k++)
            s = fmaf(t0[k], w1[k * ND + c], s);
        hout[node * ND + c] = fmaxf(s, ALPHAV * s);
    }
}

// ---------------------------------------------------------------------------
// out = tanh(h @ out_w + out_b)
// ---------------------------------------------------------------------------
__global__ void out_kernel(const float* __restrict__ h,
                           const float* __restrict__ w,
                           const float* __restrict__ b,
                           float* __restrict__ out)
{
    int idx = blockIdx.x * blockDim.x + threadIdx.x;
    if (idx >= BB * NN * 3) return;
    int node = idx / 3, o = idx % 3;
    float acc = b[o];
    #pragma unroll
    for (int k = 0; k < ND; k++)
        acc = fmaf(h[node * ND + k], w[k * 3 + o], acc);
    out[idx] = tanhf(acc);
}

// ---------------------------------------------------------------------------
extern "C" void kernel_launch(void* const* d_in, const int* in_sizes, int n_in,
                              void* d_out, int out_size)
{
    const float* x     = (const float*)d_in[0];
    const float* lin_w = (const float*)d_in[1];
    const float* lin_b = (const float*)d_in[2];
    const float* ew0[2] = { (const float*)d_in[3],  (const float*)d_in[11] };
    const float* eb0[2] = { (const float*)d_in[4],  (const float*)d_in[12] };
    const float* ew1[2] = { (const float*)d_in[5],  (const float*)d_in[13] };
    const float* eb1[2] = { (const float*)d_in[6],  (const float*)d_in[14] };
    const float* nw0[2] = { (const float*)d_in[7],  (const float*)d_in[15] };
    const float* nb0[2] = { (const float*)d_in[8],  (const float*)d_in[16] };
    const float* nw1[2] = { (const float*)d_in[9],  (const float*)d_in[17] };
    const float* nb1[2] = { (const float*)d_in[10], (const float*)d_in[18] };
    const float* out_w = (const float*)d_in[19];
    const float* out_b = (const float*)d_in[20];
    float* out = (float*)d_out;

    float *hA, *hB;
    cudaGetSymbolAddress((void**)&hA, g_hA);
    cudaGetSymbolAddress((void**)&hB, g_hB);

    // initial linear -> hA
    lin_kernel<<<(BB * NN * LL) / 256, 256>>>(x, lin_w, lin_b);

    float* hcur = hA;
    float* hnext = hB;
    for (int s = 0; s < 2; s++) {
        uv_kernel<<<BB * NN, 128>>>(hcur, ew0[s], eb0[s]);
        dim3 eg(NN / 4, BB);
        edge_kernel<<<eg, 256>>>(hcur, ew0[s], ew1[s], eb1[s]);
        node_kernel<<<BB * NN, 64>>>(hcur, nw0[s], nb0[s], nw1[s], nb1[s], hnext);
        float* tmp = hcur; hcur = hnext; hnext = tmp;
    }

    out_kernel<<<(BB * NN * 3 + 127) / 128, 128>>>(hcur, out_w, out_b, out);
}

// round 5
// speedup vs baseline: 1.1437x; 1.1437x over previous
#include <cuda_runtime.h>
#include <math.h>

// Problem constants
#define BB   64     // batch
#define NN   100    // nodes
#define LL   32     // feature dim
#define E1   64     // edge hidden / output dim
#define NH   64     // node hidden dim
#define ND   32     // node output dim
#define ALPHAV 0.1f

// Scratch (device globals — no allocation allowed)
__device__ float g_hA[BB*NN*LL];
__device__ float g_hB[BB*NN*LL];
__device__ float g_U [BB*NN*E1];
__device__ float g_V [BB*NN*E1];
__device__ float g_agg[BB*NN*E1];

__device__ __forceinline__ float lrelu(float x) { return fmaxf(x, ALPHAV * x); }

// ---------------------------------------------------------------------------
// h = (x @ lin_w + lin_b).reshape(B, N, L)   -> g_hA
// ---------------------------------------------------------------------------
__global__ void lin_kernel(const float* __restrict__ x,
                           const float* __restrict__ w,
                           const float* __restrict__ b)
{
    int idx = blockIdx.x * blockDim.x + threadIdx.x;   // < B*3200
    int bb  = idx / (NN * LL);
    int o   = idx % (NN * LL);
    float acc = b[o];
    #pragma unroll
    for (int k = 0; k < LL; k++)
        acc = fmaf(x[bb * LL + k], w[k * (NN * LL) + o], acc);
    g_hA[idx] = acc;
}

// ---------------------------------------------------------------------------
// Per-node edge-layer0 partials:
//   U[n,c] = b0[c] + sum_m h[n,m] * W0[m,c]          (xi rows 0..31)
//   V[n,c] =         sum_m h[n,m] * W0[32+m,c]       (xj rows 32..63)
// ---------------------------------------------------------------------------
__global__ void uv_kernel(const float* __restrict__ h,
                          const float* __restrict__ w0,
                          const float* __restrict__ b0)
{
    int node = blockIdx.x;          // < B*N
    int t    = threadIdx.x;         // 128 threads
    __shared__ float hs[LL];
    if (t < LL) hs[t] = h[node * LL + t];
    __syncthreads();

    int c = t & 63;
    const float* w = w0 + ((t < 64) ? 0 : (LL * E1));
    float acc = (t < 64) ? b0[c] : 0.0f;
    #pragma unroll
    for (int m = 0; m < LL; m++)
        acc = fmaf(hs[m], w[m * E1 + c], acc);
    if (t < 64) g_U[node * E1 + c] = acc;
    else        g_V[node * E1 + c] = acc;
}

// ---------------------------------------------------------------------------
// Edge kernel (f32x2 packed): for each (b, i),
//   agg[b,i,c] = sum_j lrelu( lrelu(U_i + V_j + dist(i,j)*wd) @ W1 + b1 )[c]
// Block: 4 i-values (groups of 64 channel-threads), 256 threads, 4 j's/iter.
// ---------------------------------------------------------------------------
__global__ __launch_bounds__(256, 1)
void edge_kernel(const float* __restrict__ h,
                 const float* __restrict__ ew0,   // (65,64) — only dist row used
                 const float* __restrict__ ew1,   // (64,64)
                 const float* __restrict__ eb1)   // (64)
{
    __shared__ float hjs[NN][LL + 1];                      // 13200 B
    __shared__ float Vs[NN][E1];                           // 25600 B
    __shared__ __align__(16) float dists[4][NN];           //  1600 B
    __shared__ __align__(16) float act4[4][2][E1][4];      //  8192 B  (double-buffered)

    int bb = blockIdx.y;                 // batch
    int i0 = blockIdx.x * 4;             // first node of this block
    int t  = threadIdx.x;
    int g  = t >> 6;                     // group 0..3
    int c  = t & 63;                     // channel
    int i  = i0 + g;                     // this group's node

    // Stage h rows and V rows for batch bb
    for (int idx = t; idx < NN * LL; idx += 256) {
        int j = idx / LL, m = idx % LL;
        hjs[j][m] = h[(bb * NN + j) * LL + m];
    }
    for (int idx = t; idx < NN * E1; idx += 256)
        Vs[idx >> 6][idx & 63] = g_V[bb * NN * E1 + idx];

    float Uik = g_U[(bb * NN + i) * E1 + c];  // includes b0
    float wdc = ew0[64 * E1 + c];             // dist weight row
    float b1c = eb1[c];

    // W1 column c packed {w,w} in 128 registers
    unsigned long long wp[E1];
    #pragma unroll
    for (int k = 0; k < E1; k++) {
        float w = ew1[k * E1 + c];
        asm("mov.b64 %0, {%1, %1};" : "=l"(wp[k]) : "f"(w));
    }
    unsigned long long b1p;
    asm("mov.b64 %0, {%1, %1};" : "=l"(b1p) : "f"(b1c));
    __syncthreads();

    // dist(i, j) for all j (per group)
    for (int j = c; j < NN; j += 64) {
        float s = 0.0f;
        #pragma unroll
        for (int m = 0; m < LL; m++) {
            float d = hjs[j][m] - hjs[i][m];
            s = fmaf(d, d, s);
        }
        dists[g][j] = sqrtf(s + 1e-12f);
    }
    __syncthreads();

    float aggc = 0.0f;
    #pragma unroll 1
    for (int j0 = 0; j0 < NN; j0 += 4) {
        int buf = (j0 >> 2) & 1;
        // layer0 for 4 j's (factored): one channel per thread
        float4 dv = *reinterpret_cast<const float4*>(&dists[g][j0]);
        float t0v = fmaf(dv.x, wdc, Uik + Vs[j0 + 0][c]);
        float t1v = fmaf(dv.y, wdc, Uik + Vs[j0 + 1][c]);
        float t2v = fmaf(dv.z, wdc, Uik + Vs[j0 + 2][c]);
        float t3v = fmaf(dv.w, wdc, Uik + Vs[j0 + 3][c]);
        float4 av;
        av.x = fmaxf(t0v, ALPHAV * t0v);
        av.y = fmaxf(t1v, ALPHAV * t1v);
        av.z = fmaxf(t2v, ALPHAV * t2v);
        av.w = fmaxf(t3v, ALPHAV * t3v);
        *reinterpret_cast<float4*>(&act4[g][buf][c][0]) = av;
        __syncthreads();   // single barrier per 4 j's (double-buffered act4)

        // layer1: packed fp32x2, 2 independent chains, broadcast LDS.128 per k
        unsigned long long s01 = b1p, s23 = b1p;
        const ulonglong2* ap = reinterpret_cast<const ulonglong2*>(&act4[g][buf][0][0]);
        #pragma unroll
        for (int k = 0; k < E1; k++) {
            ulonglong2 a = ap[k];
            asm("fma.rn.f32x2 %0, %1, %2, %0;" : "+l"(s01) : "l"(a.x), "l"(wp[k]));
            asm("fma.rn.f32x2 %0, %1, %2, %0;" : "+l"(s23) : "l"(a.y), "l"(wp[k]));
        }
        float r0, r1, r2, r3;
        asm("mov.b64 {%0, %1}, %2;" : "=f"(r0), "=f"(r1) : "l"(s01));
        asm("mov.b64 {%0, %1}, %2;" : "=f"(r2), "=f"(r3) : "l"(s23));
        aggc += fmaxf(r0, ALPHAV * r0);
        aggc += fmaxf(r1, ALPHAV * r1);
        aggc += fmaxf(r2, ALPHAV * r2);
        aggc += fmaxf(r3, ALPHAV * r3);
    }
    g_agg[(bb * NN + i) * E1 + c] = aggc;
}

// ---------------------------------------------------------------------------
// Node MLP: h_out = lrelu( lrelu( [h, agg] @ W0 + b0 ) @ W1 + b1 )
// 4 nodes per block, weights staged in smem.
// ---------------------------------------------------------------------------
__global__ __launch_bounds__(256)
void node_kernel(const float* __restrict__ h,
                 const float* __restrict__ w0,
                 const float* __restrict__ b0,
                 const float* __restrict__ w1,
                 const float* __restrict__ b1,
                 float* __restrict__ hout)
{
    __shared__ float w0s[(LL + E1) * NH];   // 96*64
    __shared__ float w1s[NH * ND];          // 64*32
    __shared__ float z[4][LL + E1];
    __shared__ float t0[4][NH];

    int t = threadIdx.x, g = t >> 6, c = t & 63;
    int node = blockIdx.x * 4 + g;

    for (int i = t; i < (LL + E1) * NH; i += 256) w0s[i] = w0[i];
    for (int i = t; i < NH * ND; i += 256)        w1s[i] = w1[i];
    if (c < LL) z[g][c] = h[node * LL + c];
    z[g][LL + c] = g_agg[node * E1 + c];
    __syncthreads();

    float acc = b0[c];
    #pragma unroll
    for (int m = 0; m < LL + E1; m++)
        acc = fmaf(z[g][m], w0s[m * NH + c], acc);
    t0[g][c] = fmaxf(acc, ALPHAV * acc);
    __syncthreads();

    if (c < ND) {
        float s = b1[c];
        #pragma unroll
        for (int k = 0; k < NH; k++)
            s = fmaf(t0[g][k], w1s[k * ND + c], s);
        hout[node * ND + c] = fmaxf(s, ALPHAV * s);
    }
}

// ---------------------------------------------------------------------------
// out = tanh(h @ out_w + out_b)
// ---------------------------------------------------------------------------
__global__ void out_kernel(const float* __restrict__ h,
                           const float* __restrict__ w,
                           const float* __restrict__ b,
                           float* __restrict__ out)
{
    int idx = blockIdx.x * blockDim.x + threadIdx.x;
    if (idx >= BB * NN * 3) return;
    int node = idx / 3, o = idx % 3;
    float acc = b[o];
    #pragma unroll
    for (int k = 0; k < ND; k++)
        acc = fmaf(h[node * ND + k], w[k * 3 + o], acc);
    out[idx] = tanhf(acc);
}

// ---------------------------------------------------------------------------
extern "C" void kernel_launch(void* const* d_in, const int* in_sizes, int n_in,
                              void* d_out, int out_size)
{
    const float* x     = (const float*)d_in[0];
    const float* lin_w = (const float*)d_in[1];
    const float* lin_b = (const float*)d_in[2];
    const float* ew0[2] = { (const float*)d_in[3],  (const float*)d_in[11] };
    const float* eb0[2] = { (const float*)d_in[4],  (const float*)d_in[12] };
    const float* ew1[2] = { (const float*)d_in[5],  (const float*)d_in[13] };
    const float* eb1[2] = { (const float*)d_in[6],  (const float*)d_in[14] };
    const float* nw0[2] = { (const float*)d_in[7],  (const float*)d_in[15] };
    const float* nb0[2] = { (const float*)d_in[8],  (const float*)d_in[16] };
    const float* nw1[2] = { (const float*)d_in[9],  (const float*)d_in[17] };
    const float* nb1[2] = { (const float*)d_in[10], (const float*)d_in[18] };
    const float* out_w = (const float*)d_in[19];
    const float* out_b = (const float*)d_in[20];
    float* out = (float*)d_out;

    float *hA, *hB;
    cudaGetSymbolAddress((void**)&hA, g_hA);
    cudaGetSymbolAddress((void**)&hB, g_hB);

    lin_kernel<<<(BB * NN * LL) / 256, 256>>>(x, lin_w, lin_b);

    float* hcur = hA;
    float* hnext = hB;
    for (int s = 0; s < 2; s++) {
        uv_kernel<<<BB * NN, 128>>>(hcur, ew0[s], eb0[s]);
        dim3 eg(NN / 4, BB);
        edge_kernel<<<eg, 256>>>(hcur, ew0[s], ew1[s], eb1[s]);
        node_kernel<<<(BB * NN) / 4, 256>>>(hcur, nw0[s], nb0[s], nw1[s], nb1[s], hnext);
        float* tmp = hcur; hcur = hnext; hnext = tmp;
    }

    out_kernel<<<(BB * NN * 3 + 127) / 128, 128>>>(hcur, out_w, out_b, out);
}

// round 6
// speedup vs baseline: 2.4943x; 2.1809x over previous
#include <cuda_runtime.h>
#include <math.h>

// Problem constants
#define BB   64     // batch
#define NN   100    // nodes
#define LL   32     // feature dim
#define E1   64     // edge hidden / output dim
#define NH   64     // node hidden dim
#define ND   32     // node output dim
#define ALPHAV 0.1f

// Scratch (device globals — no allocation allowed)
__device__ float g_hA[BB*NN*LL];
__device__ float g_hB[BB*NN*LL];
__device__ float g_U [BB*NN*E1];
__device__ float g_V [BB*NN*E1];
__device__ float g_agg[BB*NN*E1];

__device__ __forceinline__ float lrelu(float x) { return fmaxf(x, ALPHAV * x); }
__device__ __forceinline__ unsigned f2tf32(float x) {
    unsigned u;
    asm("cvt.rna.tf32.f32 %0, %1;" : "=r"(u) : "f"(x));
    return u;
}

// ---------------------------------------------------------------------------
// h = (x @ lin_w + lin_b).reshape(B, N, L)   -> g_hA
// ---------------------------------------------------------------------------
__global__ void lin_kernel(const float* __restrict__ x,
                           const float* __restrict__ w,
                           const float* __restrict__ b)
{
    int idx = blockIdx.x * blockDim.x + threadIdx.x;   // < B*3200
    int bb  = idx / (NN * LL);
    int o   = idx % (NN * LL);
    float acc = b[o];
    #pragma unroll
    for (int k = 0; k < LL; k++)
        acc = fmaf(x[bb * LL + k], w[k * (NN * LL) + o], acc);
    g_hA[idx] = acc;
}

// ---------------------------------------------------------------------------
// Per-node edge-layer0 partials. 16 nodes/block, weights staged in smem,
// each weight element reused across 8 nodes held in registers.
//   U[n,c] = b0[c] + sum_m h[n,m] * W0[m,c]
//   V[n,c] =         sum_m h[n,m] * W0[32+m,c]
// ---------------------------------------------------------------------------
__global__ __launch_bounds__(256)
void uv_kernel(const float* __restrict__ h,
               const float* __restrict__ w0,
               const float* __restrict__ b0)
{
    __shared__ float w0s[64 * 64];     // rows 0..63 of ew0 (16KB)
    __shared__ float hs[16][33];
    int tid = threadIdx.x;
    int n0 = blockIdx.x * 16;

    for (int p = tid; p < 64 * 64; p += 256) w0s[p] = w0[p];
    for (int p = tid; p < 16 * LL; p += 256) {
        int nl = p >> 5, m = p & 31;
        hs[nl][m] = h[(n0 + nl) * LL + m];
    }
    __syncthreads();

    int c     = tid & 63;
    int half  = (tid >> 6) & 1;       // 0 -> U, 1 -> V
    int nh    = tid >> 7;             // node-group 0/1
    const float* wp = w0s + half * (LL * 64);
    float bias = half ? 0.0f : b0[c];

    float acc[8];
    #pragma unroll
    for (int s = 0; s < 8; s++) acc[s] = bias;
    #pragma unroll
    for (int m = 0; m < LL; m++) {
        float wv = wp[m * 64 + c];
        #pragma unroll
        for (int s = 0; s < 8; s++)
            acc[s] = fmaf(hs[nh * 8 + s][m], wv, acc[s]);
    }
    float* dst = half ? g_V : g_U;
    #pragma unroll
    for (int s = 0; s < 8; s++)
        dst[(n0 + nh * 8 + s) * E1 + c] = acc[s];
}

// ---------------------------------------------------------------------------
// Edge kernel — tensor-core layer-1 (tf32 mma.sync m16n8k8).
// Block = 128 threads = 4 warps, one warp per node i (4 i's/block).
// Per warp: for each 16-j tile, build act0[16][64] (fp32 math, tf32-rounded)
// in a private smem buffer, run 8x8 = 64 mma, lrelu + masked row-sum in
// registers, shfl-reduce once at the end.
// ---------------------------------------------------------------------------
__global__ __launch_bounds__(128)
void edge_kernel(const float* __restrict__ h,
                 const float* __restrict__ ew0,   // (65,64): row 64 = dist weights
                 const float* __restrict__ ew1,   // (64,64)
                 const float* __restrict__ eb1)   // (64)
{
    // pool: first used as hjs[100][33] (dist phase), then act0 buffers
    __shared__ __align__(16) float pool[4 * 16 * 68];   // 17408 B
    __shared__ __align__(16) float w1f[4096];           // 16384 B, frag-ordered tf32
    __shared__ __align__(16) float dists_s[4][112];

    const int bb   = blockIdx.y;
    const int i0   = blockIdx.x * 4;
    const int tid  = threadIdx.x;
    const int w    = tid >> 5;
    const int lane = tid & 31;
    const int i    = i0 + w;
    const int q    = lane & 3;        // quad index (col group)
    const int r    = lane >> 2;       // row index 0..7

    // ---- stage hjs (union with act0 pool) ----
    float (*hjs)[33] = reinterpret_cast<float(*)[33]>(pool);
    for (int idx = tid; idx < NN * LL; idx += 128) {
        int j = idx >> 5, m = idx & 31;
        hjs[j][m] = h[(bb * NN + j) * LL + m];
    }
    // ---- repack W1 into fragment order (tf32-rounded) ----
    for (int p = tid; p < 2048; p += 128) {
        int frag = p >> 5, fl = p & 31;
        int kt = frag >> 3, nt = frag & 7, fq = fl & 3, cl = fl >> 2;
        float v0 = ew1[(kt * 8 + fq    ) * 64 + nt * 8 + cl];
        float v1 = ew1[(kt * 8 + fq + 4) * 64 + nt * 8 + cl];
        w1f[2 * p    ] = __uint_as_float(f2tf32(v0));
        w1f[2 * p + 1] = __uint_as_float(f2tf32(v1));
    }
    __syncthreads();

    // ---- distances for this warp's i ----
    for (int j = lane; j < NN; j += 32) {
        float s = 0.0f;
        #pragma unroll
        for (int m = 0; m < LL; m++) {
            float d = hjs[j][m] - hjs[i][m];
            s = fmaf(d, d, s);
        }
        dists_s[w][j] = sqrtf(s + 1e-12f);
    }
    __syncthreads();   // everyone done reading hjs before act0 overwrites pool

    // ---- per-thread constants ----
    const int kk = 4 * (lane & 15);   // k base this thread fills in act0
    const int tb = lane >> 4;         // 0/1 (which j of the pair per m-step)
    float4 U4  = *reinterpret_cast<const float4*>(&g_U[(bb * NN + i) * E1 + kk]);
    float4 wd4 = *reinterpret_cast<const float4*>(&ew0[64 * E1 + kk]);
    float b1a[8], b1b[8];
    #pragma unroll
    for (int nt = 0; nt < 8; nt++) {
        b1a[nt] = eb1[nt * 8 + 2 * q];
        b1b[nt] = eb1[nt * 8 + 2 * q + 1];
    }

    float* as = pool + w * (16 * 68);
    float sa[8][2];
    #pragma unroll
    for (int nt = 0; nt < 8; nt++) { sa[nt][0] = 0.0f; sa[nt][1] = 0.0f; }

    #pragma unroll 1
    for (int jb = 0; jb < 112; jb += 16) {
        // -- act0 for rows jb..jb+15 (tf32-rounded fp32) --
        #pragma unroll
        for (int m = 0; m < 8; m++) {
            int jl = 2 * m + tb;
            int jg = jb + jl; if (jg > NN - 1) jg = NN - 1;   // clamp pad rows
            float dj = dists_s[w][jg];
            float4 v = *reinterpret_cast<const float4*>(&g_V[(bb * NN + jg) * E1 + kk]);
            float a0 = fmaf(dj, wd4.x, U4.x + v.x); a0 = fmaxf(a0, ALPHAV * a0);
            float a1 = fmaf(dj, wd4.y, U4.y + v.y); a1 = fmaxf(a1, ALPHAV * a1);
            float a2 = fmaf(dj, wd4.z, U4.z + v.z); a2 = fmaxf(a2, ALPHAV * a2);
            float a3 = fmaf(dj, wd4.w, U4.w + v.w); a3 = fmaxf(a3, ALPHAV * a3);
            float4 st;
            st.x = __uint_as_float(f2tf32(a0));
            st.y = __uint_as_float(f2tf32(a1));
            st.z = __uint_as_float(f2tf32(a2));
            st.w = __uint_as_float(f2tf32(a3));
            *reinterpret_cast<float4*>(&as[jl * 68 + kk]) = st;
        }
        __syncwarp();

        // -- D init with bias --
        float d[8][4];
        #pragma unroll
        for (int nt = 0; nt < 8; nt++) {
            d[nt][0] = b1a[nt]; d[nt][1] = b1b[nt];
            d[nt][2] = b1a[nt]; d[nt][3] = b1b[nt];
        }
        // -- 8 k-tiles x 8 n-tiles mma --
        #pragma unroll
        for (int kt = 0; kt < 8; kt++) {
            int kb = kt * 8;
            unsigned a0 = __float_as_uint(as[ r      * 68 + kb + q    ]);
            unsigned a1 = __float_as_uint(as[(r + 8) * 68 + kb + q    ]);
            unsigned a2 = __float_as_uint(as[ r      * 68 + kb + q + 4]);
            unsigned a3 = __float_as_uint(as[(r + 8) * 68 + kb + q + 4]);
            #pragma unroll
            for (int nt = 0; nt < 8; nt++) {
                float2 bp = *reinterpret_cast<const float2*>(&w1f[((kt * 8 + nt) * 32 + lane) * 2]);
                unsigned bf0 = __float_as_uint(bp.x);
                unsigned bf1 = __float_as_uint(bp.y);
                asm volatile(
                    "mma.sync.aligned.m16n8k8.row.col.f32.tf32.tf32.f32 "
                    "{%0,%1,%2,%3}, {%4,%5,%6,%7}, {%8,%9}, {%0,%1,%2,%3};"
                    : "+f"(d[nt][0]), "+f"(d[nt][1]), "+f"(d[nt][2]), "+f"(d[nt][3])
                    : "r"(a0), "r"(a1), "r"(a2), "r"(a3), "r"(bf0), "r"(bf1));
            }
        }
        __syncwarp();   // mma A-reads done before next tile's stores

        // -- epilogue: lrelu + masked row accumulation --
        bool v0 = (jb + r)     < NN;
        bool v1 = (jb + r + 8) < NN;
        #pragma unroll
        for (int nt = 0; nt < 8; nt++) {
            float l0 = fmaxf(d[nt][0], ALPHAV * d[nt][0]);
            float l1 = fmaxf(d[nt][1], ALPHAV * d[nt][1]);
            float l2 = fmaxf(d[nt][2], ALPHAV * d[nt][2]);
            float l3 = fmaxf(d[nt][3], ALPHAV * d[nt][3]);
            if (v0) { sa[nt][0] += l0; sa[nt][1] += l1; }
            if (v1) { sa[nt][0] += l2; sa[nt][1] += l3; }
        }
    }

    // ---- reduce over rows (lanes differing in bits 2..4), write agg ----
    #pragma unroll
    for (int nt = 0; nt < 8; nt++) {
        #pragma unroll
        for (int e = 0; e < 2; e++) {
            float v = sa[nt][e];
            v += __shfl_xor_sync(0xffffffff, v, 4);
            v += __shfl_xor_sync(0xffffffff, v, 8);
            v += __shfl_xor_sync(0xffffffff, v, 16);
            sa[nt][e] = v;
        }
    }
    if (lane < 4) {
        #pragma unroll
        for (int nt = 0; nt < 8; nt++) {
            float2 st = make_float2(sa[nt][0], sa[nt][1]);
            *reinterpret_cast<float2*>(&g_agg[(bb * NN + i) * E1 + nt * 8 + 2 * q]) = st;
        }
    }
}

// ---------------------------------------------------------------------------
// Node MLP: h_out = lrelu( lrelu( [h, agg] @ W0 + b0 ) @ W1 + b1 )
// 8 nodes per block (512 threads), weights staged in smem once.
// ---------------------------------------------------------------------------
__global__ __launch_bounds__(512)
void node_kernel(const float* __restrict__ h,
                 const float* __restrict__ w0,
                 const float* __restrict__ b0,
                 const float* __restrict__ w1,
                 const float* __restrict__ b1,
                 float* __restrict__ hout)
{
    __shared__ float w0s[(LL + E1) * NH];   // 24KB
    __shared__ float w1s[NH * ND];          // 8KB
    __shared__ float z[8][100];
    __shared__ float t0s[8][NH];

    int t = threadIdx.x, g = t >> 6, c = t & 63;
    int node = blockIdx.x * 8 + g;

    for (int p = t; p < (LL + E1) * NH; p += 512) w0s[p] = w0[p];
    for (int p = t; p < NH * ND; p += 512)        w1s[p] = w1[p];
    if (c < LL) z[g][c] = h[node * LL + c];
    z[g][LL + c] = g_agg[node * E1 + c];
    __syncthreads();

    // layer 0: two partial chains for ILP
    float acc0 = b0[c], acc1 = 0.0f;
    #pragma unroll
    for (int m = 0; m < LL + E1; m += 2) {
        acc0 = fmaf(z[g][m],     w0s[ m      * NH + c], acc0);
        acc1 = fmaf(z[g][m + 1], w0s[(m + 1) * NH + c], acc1);
    }
    float a = acc0 + acc1;
    t0s[g][c] = fmaxf(a, ALPHAV * a);
    __syncthreads();

    if (c < ND) {
        float s0 = b1[c], s1 = 0.0f;
        #pragma unroll
        for (int k = 0; k < NH; k += 2) {
            s0 = fmaf(t0s[g][k],     w1s[ k      * ND + c], s0);
            s1 = fmaf(t0s[g][k + 1], w1s[(k + 1) * ND + c], s1);
        }
        float s = s0 + s1;
        hout[node * ND + c] = fmaxf(s, ALPHAV * s);
    }
}

// ---------------------------------------------------------------------------
// out = tanh(h @ out_w + out_b)
// ---------------------------------------------------------------------------
__global__ void out_kernel(const float* __restrict__ h,
                           const float* __restrict__ w,
                           const float* __restrict__ b,
                           float* __restrict__ out)
{
    int idx = blockIdx.x * blockDim.x + threadIdx.x;
    if (idx >= BB * NN * 3) return;
    int node = idx / 3, o = idx % 3;
    float acc = b[o];
    #pragma unroll
    for (int k = 0; k < ND; k++)
        acc = fmaf(h[node * ND + k], w[k * 3 + o], acc);
    out[idx] = tanhf(acc);
}

// ---------------------------------------------------------------------------
extern "C" void kernel_launch(void* const* d_in, const int* in_sizes, int n_in,
                              void* d_out, int out_size)
{
    const float* x     = (const float*)d_in[0];
    const float* lin_w = (const float*)d_in[1];
    const float* lin_b = (const float*)d_in[2];
    const float* ew0[2] = { (const float*)d_in[3],  (const float*)d_in[11] };
    const float* eb0[2] = { (const float*)d_in[4],  (const float*)d_in[12] };
    const float* ew1[2] = { (const float*)d_in[5],  (const float*)d_in[13] };
    const float* eb1[2] = { (const float*)d_in[6],  (const float*)d_in[14] };
    const float* nw0[2] = { (const float*)d_in[7],  (const float*)d_in[15] };
    const float* nb0[2] = { (const float*)d_in[8],  (const float*)d_in[16] };
    const float* nw1[2] = { (const float*)d_in[9],  (const float*)d_in[17] };
    const float* nb1[2] = { (const float*)d_in[10], (const float*)d_in[18] };
    const float* out_w = (const float*)d_in[19];
    const float* out_b = (const float*)d_in[20];
    float* out = (float*)d_out;

    float *hA, *hB;
    cudaGetSymbolAddress((void**)&hA, g_hA);
    cudaGetSymbolAddress((void**)&hB, g_hB);

    lin_kernel<<<(BB * NN * LL) / 256, 256>>>(x, lin_w, lin_b);

    float* hcur = hA;
    float* hnext = hB;
    for (int s = 0; s < 2; s++) {
        uv_kernel<<<(BB * NN) / 16, 256>>>(hcur, ew0[s], eb0[s]);
        dim3 eg(NN / 4, BB);
        edge_kernel<<<eg, 128>>>(hcur, ew0[s], ew1[s], eb1[s]);
        node_kernel<<<(BB * NN) / 8, 512>>>(hcur, nw0[s], nb0[s], nw1[s], nb1[s], hnext);
        float* tmp = hcur; hcur = hnext; hnext = tmp;
    }

    out_kernel<<<(BB * NN * 3 + 127) / 128, 128>>>(hcur, out_w, out_b, out);
}